// round 9
// baseline (speedup 1.0000x reference)
#include <cuda_runtime.h>
#include <cuda_bf16.h>
#include <cstdint>

// Batched Newton-Schulz matrix sqrt: 1024 x (128x128 fp32), 5 iterations.
// mma.sync bf16 + ldmatrix, fp32 via hi+lo split (hh+hl+lh), triangular
// outputs + mirror. m32n32 warp tiles amortize B-fragment reads; P2 pairs
// Y@T with Z@T sharing B (=T) fragments -> 128 B smem read per MMA.

#define NMAT 128
#define NT 384
#define PITCH32 68      // u32 words per smem row
#define PITCHB 272      // bytes per smem row
#define PITCH16 136

__device__ __forceinline__ void mma16816(float* d, const uint32_t* a,
                                         const uint32_t* b) {
    asm volatile(
        "mma.sync.aligned.m16n8k16.row.col.f32.bf16.bf16.f32 "
        "{%0,%1,%2,%3}, {%4,%5,%6,%7}, {%8,%9}, {%0,%1,%2,%3};"
        : "+f"(d[0]), "+f"(d[1]), "+f"(d[2]), "+f"(d[3])
        : "r"(a[0]), "r"(a[1]), "r"(a[2]), "r"(a[3]), "r"(b[0]), "r"(b[1]));
}

#define LDSM4(r_, a_)                                                         \
    asm volatile("ldmatrix.sync.aligned.m8n8.x4.shared.b16 {%0,%1,%2,%3}, [%4];" \
                 : "=r"((r_)[0]), "=r"((r_)[1]), "=r"((r_)[2]), "=r"((r_)[3])  \
                 : "r"(a_))

__device__ __forceinline__ uint32_t sp(const void* p) {
    return (uint32_t)__cvta_generic_to_shared(p);
}

__device__ __forceinline__ void split2f(float v0, float v1, uint32_t& hw,
                                        uint32_t& lw) {
    asm("cvt.rn.bf16x2.f32 %0, %1, %2;" : "=r"(hw) : "f"(v1), "f"(v0));
    float h0 = __uint_as_float(hw << 16);
    float h1 = __uint_as_float(hw & 0xffff0000u);
    float l0 = v0 - h0, l1 = v1 - h1;
    asm("cvt.rn.bf16x2.f32 %0, %1, %2;" : "=r"(lw) : "f"(l1), "f"(l0));
}

__device__ __forceinline__ void zero4(float a[4][4]) {
#pragma unroll
    for (int i = 0; i < 4; i++)
#pragma unroll
        for (int j = 0; j < 4; j++) a[i][j] = 0.f;
}

// ldmatrix octet addressing
__device__ __forceinline__ uint32_t a_off(int r0, int lane) {
    return (uint32_t)((r0 + (lane & 7) + ((lane >> 3) & 1) * 8) * PITCHB +
                      (lane >> 4) * 16);
}
__device__ __forceinline__ uint32_t b_off(int c0, int lane) {
    return (uint32_t)((c0 + (lane & 7) + (lane >> 4) * 8) * PITCHB +
                      ((lane >> 3) & 1) * 16);
}

// m16n32 single product: acc += Ph@Qh + Ph@Ql + Pl@Qh
__device__ __forceinline__ void mm16(const uint32_t* Ph, const uint32_t* Pl,
                                     const uint32_t* Qh, const uint32_t* Ql,
                                     float acc[4][4], int r0, int c0, int lane) {
    const uint32_t ao = a_off(r0, lane), bo = b_off(c0, lane);
    uint32_t pah = sp(Ph) + ao, pal = sp(Pl) + ao;
    uint32_t qh0 = sp(Qh) + bo, qh1 = qh0 + 16 * PITCHB;
    uint32_t ql0 = sp(Ql) + bo, ql1 = ql0 + 16 * PITCHB;
#pragma unroll
    for (int k = 0; k < 8; k++) {
        uint32_t ah[4], al[4], bh[8], bl[8];
        LDSM4(ah, pah); LDSM4(al, pal);
        LDSM4(bh, qh0); LDSM4(bh + 4, qh1);
        LDSM4(bl, ql0); LDSM4(bl + 4, ql1);
        pah += 32; pal += 32; qh0 += 32; qh1 += 32; ql0 += 32; ql1 += 32;
#pragma unroll
        for (int ni = 0; ni < 4; ni++) {
            mma16816(acc[ni], ah, bh + ni * 2);
            mma16816(acc[ni], ah, bl + ni * 2);
            mma16816(acc[ni], al, bh + ni * 2);
        }
    }
}

// m32n32 single product (B amortized over 32 rows)
__device__ __forceinline__ void mm32(const uint32_t* Ph, const uint32_t* Pl,
                                     const uint32_t* Qh, const uint32_t* Ql,
                                     float acc[2][4][4], int r0, int c0,
                                     int lane) {
    const uint32_t ao0 = a_off(r0, lane), ao1 = a_off(r0 + 16, lane);
    const uint32_t bo = b_off(c0, lane);
    uint32_t ph0 = sp(Ph) + ao0, ph1 = sp(Ph) + ao1;
    uint32_t pl0 = sp(Pl) + ao0, pl1 = sp(Pl) + ao1;
    uint32_t qh0 = sp(Qh) + bo, qh1 = qh0 + 16 * PITCHB;
    uint32_t ql0 = sp(Ql) + bo, ql1 = ql0 + 16 * PITCHB;
#pragma unroll
    for (int k = 0; k < 8; k++) {
        uint32_t ah[2][4], al[2][4], bh[8], bl[8];
        LDSM4(ah[0], ph0); LDSM4(ah[1], ph1);
        LDSM4(al[0], pl0); LDSM4(al[1], pl1);
        LDSM4(bh, qh0); LDSM4(bh + 4, qh1);
        LDSM4(bl, ql0); LDSM4(bl + 4, ql1);
        ph0 += 32; ph1 += 32; pl0 += 32; pl1 += 32;
        qh0 += 32; qh1 += 32; ql0 += 32; ql1 += 32;
#pragma unroll
        for (int ni = 0; ni < 4; ni++)
#pragma unroll
            for (int mi = 0; mi < 2; mi++) {
                mma16816(acc[mi][ni], ah[mi], bh + ni * 2);
                mma16816(acc[mi][ni], ah[mi], bl + ni * 2);
                mma16816(acc[mi][ni], al[mi], bh + ni * 2);
            }
    }
}

// m16n32 paired: accY += Y@T, accZ += Z@T (shared B)
__device__ __forceinline__ void mmp16(const uint32_t* Yh, const uint32_t* Yl,
                                      const uint32_t* Zh, const uint32_t* Zl,
                                      const uint32_t* Th, const uint32_t* Tl,
                                      float accY[4][4], float accZ[4][4],
                                      int r0, int c0, int lane) {
    const uint32_t ao = a_off(r0, lane), bo = b_off(c0, lane);
    uint32_t pyh = sp(Yh) + ao, pyl = sp(Yl) + ao;
    uint32_t pzh = sp(Zh) + ao, pzl = sp(Zl) + ao;
    uint32_t qh0 = sp(Th) + bo, qh1 = qh0 + 16 * PITCHB;
    uint32_t ql0 = sp(Tl) + bo, ql1 = ql0 + 16 * PITCHB;
#pragma unroll
    for (int k = 0; k < 8; k++) {
        uint32_t ayh[4], ayl[4], azh[4], azl[4], bh[8], bl[8];
        LDSM4(ayh, pyh); LDSM4(ayl, pyl);
        LDSM4(azh, pzh); LDSM4(azl, pzl);
        LDSM4(bh, qh0); LDSM4(bh + 4, qh1);
        LDSM4(bl, ql0); LDSM4(bl + 4, ql1);
        pyh += 32; pyl += 32; pzh += 32; pzl += 32;
        qh0 += 32; qh1 += 32; ql0 += 32; ql1 += 32;
#pragma unroll
        for (int ni = 0; ni < 4; ni++) {
            mma16816(accY[ni], ayh, bh + ni * 2);
            mma16816(accY[ni], ayh, bl + ni * 2);
            mma16816(accY[ni], ayl, bh + ni * 2);
            mma16816(accZ[ni], azh, bh + ni * 2);
            mma16816(accZ[ni], azh, bl + ni * 2);
            mma16816(accZ[ni], azl, bh + ni * 2);
        }
    }
}

// m32n32 paired: accY += Y@T, accZ += Z@T (shared B over 32 rows)
__device__ __forceinline__ void mmp32(const uint32_t* Yh, const uint32_t* Yl,
                                      const uint32_t* Zh, const uint32_t* Zl,
                                      const uint32_t* Th, const uint32_t* Tl,
                                      float accY[2][4][4], float accZ[2][4][4],
                                      int r0, int c0, int lane) {
    const uint32_t ao0 = a_off(r0, lane), ao1 = a_off(r0 + 16, lane);
    const uint32_t bo = b_off(c0, lane);
    uint32_t pyh0 = sp(Yh) + ao0, pyh1 = sp(Yh) + ao1;
    uint32_t pyl0 = sp(Yl) + ao0, pyl1 = sp(Yl) + ao1;
    uint32_t pzh0 = sp(Zh) + ao0, pzh1 = sp(Zh) + ao1;
    uint32_t pzl0 = sp(Zl) + ao0, pzl1 = sp(Zl) + ao1;
    uint32_t qh0 = sp(Th) + bo, qh1 = qh0 + 16 * PITCHB;
    uint32_t ql0 = sp(Tl) + bo, ql1 = ql0 + 16 * PITCHB;
#pragma unroll
    for (int k = 0; k < 8; k++) {
        uint32_t ayh[2][4], ayl[2][4], azh[2][4], azl[2][4], bh[8], bl[8];
        LDSM4(ayh[0], pyh0); LDSM4(ayh[1], pyh1);
        LDSM4(ayl[0], pyl0); LDSM4(ayl[1], pyl1);
        LDSM4(azh[0], pzh0); LDSM4(azh[1], pzh1);
        LDSM4(azl[0], pzl0); LDSM4(azl[1], pzl1);
        LDSM4(bh, qh0); LDSM4(bh + 4, qh1);
        LDSM4(bl, ql0); LDSM4(bl + 4, ql1);
        pyh0 += 32; pyh1 += 32; pyl0 += 32; pyl1 += 32;
        pzh0 += 32; pzh1 += 32; pzl0 += 32; pzl1 += 32;
        qh0 += 32; qh1 += 32; ql0 += 32; ql1 += 32;
#pragma unroll
        for (int ni = 0; ni < 4; ni++)
#pragma unroll
            for (int mi = 0; mi < 2; mi++) {
                mma16816(accY[mi][ni], ayh[mi], bh + ni * 2);
                mma16816(accY[mi][ni], ayh[mi], bl + ni * 2);
                mma16816(accY[mi][ni], ayl[mi], bh + ni * 2);
                mma16816(accZ[mi][ni], azh[mi], bh + ni * 2);
                mma16816(accZ[mi][ni], azh[mi], bl + ni * 2);
                mma16816(accZ[mi][ni], azl[mi], bh + ni * 2);
            }
    }
}

// v = alpha*acc + beta*I -> hi/lo pair; optional mirror to transposed pos.
__device__ __forceinline__ void epi_half(const float acc[4][4],
                                         uint32_t* __restrict__ Bh,
                                         uint32_t* __restrict__ Bl, float alpha,
                                         float beta, int r0, int c0, int lane,
                                         bool mir) {
    const int qr = lane >> 2, cp = (lane & 3) * 2;
    uint16_t* H16 = (uint16_t*)Bh;
    uint16_t* L16 = (uint16_t*)Bl;
#pragma unroll
    for (int ni = 0; ni < 4; ni++) {
        const int col = c0 + ni * 8 + cp;
#pragma unroll
        for (int h = 0; h < 2; h++) {
            const int row = r0 + qr + h * 8;
            float v0 = alpha * acc[ni][2 * h]     + ((row == col)     ? beta : 0.f);
            float v1 = alpha * acc[ni][2 * h + 1] + ((row == col + 1) ? beta : 0.f);
            uint32_t hw, lw;
            split2f(v0, v1, hw, lw);
            const int idx = row * PITCH32 + (col >> 1);
            Bh[idx] = hw;
            Bl[idx] = lw;
            if (mir) {
                H16[col * PITCH16 + row]       = (uint16_t)hw;
                H16[(col + 1) * PITCH16 + row] = (uint16_t)(hw >> 16);
                L16[col * PITCH16 + row]       = (uint16_t)lw;
                L16[(col + 1) * PITCH16 + row] = (uint16_t)(lw >> 16);
            }
        }
    }
}

__device__ __forceinline__ void epi_out_half(const float acc[4][4],
                                             float* __restrict__ Ob, float s,
                                             int r0, int c0, int lane) {
    const int qr = lane >> 2, cp = (lane & 3) * 2;
#pragma unroll
    for (int ni = 0; ni < 4; ni++) {
        const int col = c0 + ni * 8 + cp;
#pragma unroll
        for (int h = 0; h < 2; h++) {
            const int row = r0 + qr + h * 8;
            *(float2*)(Ob + row * 128 + col) =
                make_float2(s * acc[ni][2 * h], s * acc[ni][2 * h + 1]);
        }
    }
}

__device__ __constant__ int LTI[10] = {0, 1, 1, 2, 2, 2, 3, 3, 3, 3};
__device__ __constant__ int LTJ[10] = {0, 0, 1, 0, 1, 2, 0, 1, 2, 3};

__global__ void __launch_bounds__(NT, 1)
ns_t32_kernel(const float* __restrict__ A, float* __restrict__ Out) {
    extern __shared__ uint32_t sm[];
    uint32_t* Yh = sm;
    uint32_t* Yl = sm + 128 * PITCH32;
    uint32_t* Zh = sm + 2 * 128 * PITCH32;
    uint32_t* Zl = sm + 3 * 128 * PITCH32;
    uint32_t* Th = sm + 4 * 128 * PITCH32;
    uint32_t* Tl = sm + 5 * 128 * PITCH32;
    __shared__ float red[12];

    const int tid = threadIdx.x, w = tid >> 5, lane = tid & 31;
    const float* Ab = A + (size_t)blockIdx.x * 16384;
    float* Ob = Out + (size_t)blockIdx.x * 16384;

    // --- Task geometry ---
    // Triangular phases: warps 0-7 own m32 tiles 0-7; warps 8-11 own m16
    // halves of tiles 8 ((3,2), mirrored) and 9 ((3,3), diagonal).
    const bool big = (w < 8);
    const int tp = big ? w : (8 + ((w - 8) >> 1));
    const int Tr = LTI[tp] * 32 + (big ? 0 : ((w - 8) & 1) * 16);
    const int Tc = LTJ[tp] * 32;
    const bool Tm = (LTI[tp] != LTJ[tp]);
    // Last full phase: warp w -> m32 tile w (of 16); w<8 also m16 half of
    // tiles 12-15. Tile t: r=(t&3)*32, c=(t>>2)*32.
    const int Lr = (w & 3) * 32, Lc = (w >> 2) * 32;
    const int Er = (w >> 1) * 32 + (w & 1) * 16, Ec = 96;

    // ---- Frobenius norm ----
    float ss = 0.f;
    const float4* A4 = (const float4*)Ab;
    for (int i = tid; i < 4096; i += NT) {
        float4 v = A4[i];
        ss = fmaf(v.x, v.x, fmaf(v.y, v.y, fmaf(v.z, v.z, fmaf(v.w, v.w, ss))));
    }
#pragma unroll
    for (int o = 16; o; o >>= 1) ss += __shfl_xor_sync(0xffffffffu, ss, o);
    if (lane == 0) red[w] = ss;
    __syncthreads();
    float tot = 0.f;
#pragma unroll
    for (int i = 0; i < 12; i++) tot += red[i];
    const float normA = sqrtf(tot);
    const float inv = 1.f / normA;

    // ---- Init: Y0 = A*inv; T1 = Z1 = 1.5I - 0.5*Y0 (all split) ----
    for (int u = tid; u < 2048; u += NT) {
        const int row = u >> 4;
        const int col = (u & 15) * 8;
        float4 a0 = *(const float4*)(Ab + row * 128 + col);
        float4 a1 = *(const float4*)(Ab + row * 128 + col + 4);
        float yv[8] = {a0.x * inv, a0.y * inv, a0.z * inv, a0.w * inv,
                       a1.x * inv, a1.y * inv, a1.z * inv, a1.w * inv};
#pragma unroll
        for (int jj = 0; jj < 4; jj++) {
            const int cc = col + 2 * jj;
            const int idx = row * PITCH32 + (cc >> 1);
            uint32_t hw, lw;
            split2f(yv[2 * jj], yv[2 * jj + 1], hw, lw);
            Yh[idx] = hw; Yl[idx] = lw;
            float q0 = -0.5f * yv[2 * jj]     + (row == cc     ? 1.5f : 0.f);
            float q1 = -0.5f * yv[2 * jj + 1] + (row == cc + 1 ? 1.5f : 0.f);
            split2f(q0, q1, hw, lw);
            Th[idx] = hw; Tl[idx] = lw;
            Zh[idx] = hw; Zl[idx] = lw;
        }
    }
    __syncthreads();

    // ---- iter 1 (reduced): Y = Y @ T1 triangular ----
    {
        float acc[2][4][4];
        zero4(acc[0]); zero4(acc[1]);
        if (big) mm32(Yh, Yl, Th, Tl, acc, Tr, Tc, lane);
        else     mm16(Yh, Yl, Th, Tl, acc[0], Tr, Tc, lane);
        __syncthreads();
        epi_half(acc[0], Yh, Yl, 1.f, 0.f, Tr, Tc, lane, Tm);
        if (big) epi_half(acc[1], Yh, Yl, 1.f, 0.f, Tr + 16, Tc, lane, Tm);
        __syncthreads();
    }

    // ---- iters 2..5 ----
#pragma unroll 1
    for (int it = 1; it < 5; ++it) {
        // P1: T = 1.5I - 0.5*(Z @ Y); epilogue fused (T not a P1 operand)
        {
            float acc[2][4][4];
            zero4(acc[0]); zero4(acc[1]);
            if (big) {
                mm32(Zh, Zl, Yh, Yl, acc, Tr, Tc, lane);
                epi_half(acc[0], Th, Tl, -0.5f, 1.5f, Tr, Tc, lane, Tm);
                epi_half(acc[1], Th, Tl, -0.5f, 1.5f, Tr + 16, Tc, lane, Tm);
            } else {
                mm16(Zh, Zl, Yh, Yl, acc[0], Tr, Tc, lane);
                epi_half(acc[0], Th, Tl, -0.5f, 1.5f, Tr, Tc, lane, Tm);
            }
        }
        __syncthreads();

        if (it < 4) {
            // P2: Y = Y@T and Z = Z@T, paired (shared B fragments)
            float ay[2][4][4], az[2][4][4];
            zero4(ay[0]); zero4(ay[1]); zero4(az[0]); zero4(az[1]);
            if (big) mmp32(Yh, Yl, Zh, Zl, Th, Tl, ay, az, Tr, Tc, lane);
            else     mmp16(Yh, Yl, Zh, Zl, Th, Tl, ay[0], az[0], Tr, Tc, lane);
            __syncthreads();
            epi_half(ay[0], Yh, Yl, 1.f, 0.f, Tr, Tc, lane, Tm);
            epi_half(az[0], Zh, Zl, 1.f, 0.f, Tr, Tc, lane, Tm);
            if (big) {
                epi_half(ay[1], Yh, Yl, 1.f, 0.f, Tr + 16, Tc, lane, Tm);
                epi_half(az[1], Zh, Zl, 1.f, 0.f, Tr + 16, Tc, lane, Tm);
            }
            __syncthreads();
        } else {
            // Last: Y5 = Y@T full grid, straight to GMEM
            const float s = sqrtf(normA);
            float acc[2][4][4];
            zero4(acc[0]); zero4(acc[1]);
            mm32(Yh, Yl, Th, Tl, acc, Lr, Lc, lane);
            epi_out_half(acc[0], Ob, s, Lr, Lc, lane);
            epi_out_half(acc[1], Ob, s, Lr + 16, Lc, lane);
            if (w < 8) {
                zero4(acc[0]);
                mm16(Yh, Yl, Th, Tl, acc[0], Er, Ec, lane);
                epi_out_half(acc[0], Ob, s, Er, Ec, lane);
            }
        }
    }
}

extern "C" void kernel_launch(void* const* d_in, const int* in_sizes, int n_in,
                              void* d_out, int out_size) {
    const float* A = (const float*)d_in[0];
    float* out = (float*)d_out;
    const int nbatch = in_sizes[0] / (NMAT * NMAT);            // 1024
    const size_t smem = 6 * 128 * PITCH32 * sizeof(uint32_t);  // 208896 B
    cudaFuncSetAttribute(ns_t32_kernel,
                         cudaFuncAttributeMaxDynamicSharedMemorySize, (int)smem);
    ns_t32_kernel<<<nbatch, NT, smem>>>(A, out);
}

// round 10
// speedup vs baseline: 1.4689x; 1.4689x over previous
#include <cuda_runtime.h>
#include <cuda_bf16.h>
#include <cstdint>

// Batched Newton-Schulz matrix sqrt: 1024 x (128x128 fp32), 5 iterations.
// mma.sync bf16 + ldmatrix, fp32 via hi+lo split (hh+hl+lh), triangular
// outputs + mirror. 12 warps, double-buffered k-loop. This rev: MMA issue
// order interleaves independent accumulator chains (dep distance 4-8).

#define NMAT 128
#define NT 384
#define PITCH32 68      // u32 words per smem row
#define PITCHB 272      // bytes per smem row
#define PITCH16 136

__device__ __forceinline__ void mma16816(float* d, const uint32_t* a,
                                         const uint32_t* b) {
    asm volatile(
        "mma.sync.aligned.m16n8k16.row.col.f32.bf16.bf16.f32 "
        "{%0,%1,%2,%3}, {%4,%5,%6,%7}, {%8,%9}, {%0,%1,%2,%3};"
        : "+f"(d[0]), "+f"(d[1]), "+f"(d[2]), "+f"(d[3])
        : "r"(a[0]), "r"(a[1]), "r"(a[2]), "r"(a[3]), "r"(b[0]), "r"(b[1]));
}

#define LDSM4(r_, a_)                                                         \
    asm volatile("ldmatrix.sync.aligned.m8n8.x4.shared.b16 {%0,%1,%2,%3}, [%4];" \
                 : "=r"((r_)[0]), "=r"((r_)[1]), "=r"((r_)[2]), "=r"((r_)[3])  \
                 : "r"(a_))

__device__ __forceinline__ uint32_t sp(const void* p) {
    return (uint32_t)__cvta_generic_to_shared(p);
}

__device__ __forceinline__ void split2f(float v0, float v1, uint32_t& hw,
                                        uint32_t& lw) {
    asm("cvt.rn.bf16x2.f32 %0, %1, %2;" : "=r"(hw) : "f"(v1), "f"(v0));
    float h0 = __uint_as_float(hw << 16);
    float h1 = __uint_as_float(hw & 0xffff0000u);
    float l0 = v0 - h0, l1 = v1 - h1;
    asm("cvt.rn.bf16x2.f32 %0, %1, %2;" : "=r"(lw) : "f"(l1), "f"(l0));
}

__device__ __forceinline__ void zero4(float a[4][4]) {
#pragma unroll
    for (int i = 0; i < 4; i++)
#pragma unroll
        for (int j = 0; j < 4; j++) a[i][j] = 0.f;
}

// ldmatrix octet addressing
__device__ __forceinline__ uint32_t a_off(int r0, int lane) {
    return (uint32_t)((r0 + (lane & 7) + ((lane >> 3) & 1) * 8) * PITCHB +
                      (lane >> 4) * 16);
}
__device__ __forceinline__ uint32_t b_off(int c0, int lane) {
    return (uint32_t)((c0 + (lane & 7) + (lane >> 4) * 8) * PITCHB +
                      ((lane >> 3) & 1) * 16);
}

// Single product acc += Ph@Qh + Ph@Ql + Pl@Qh; m16 rows r0, n32 cols c0.
// Double-buffered fragments; MMA passes interleaved over 4 indep chains.
__device__ __forceinline__ void mm_half(const uint32_t* Ph, const uint32_t* Pl,
                                        const uint32_t* Qh, const uint32_t* Ql,
                                        float acc[4][4], int r0, int c0,
                                        int lane) {
    const uint32_t ao = a_off(r0, lane), bo = b_off(c0, lane);
    uint32_t pah = sp(Ph) + ao, pal = sp(Pl) + ao;
    uint32_t qh0 = sp(Qh) + bo, qh1 = qh0 + 16 * PITCHB;
    uint32_t ql0 = sp(Ql) + bo, ql1 = ql0 + 16 * PITCHB;
    uint32_t ah[2][4], al[2][4], bh[2][8], bl[2][8];
    LDSM4(ah[0], pah); LDSM4(al[0], pal);
    LDSM4(bh[0], qh0); LDSM4(bh[0] + 4, qh1);
    LDSM4(bl[0], ql0); LDSM4(bl[0] + 4, ql1);
#pragma unroll
    for (int k = 0; k < 8; k++) {
        const int c = k & 1, n = c ^ 1;
        if (k < 7) {
            pah += 32; pal += 32; qh0 += 32; qh1 += 32; ql0 += 32; ql1 += 32;
            LDSM4(ah[n], pah); LDSM4(al[n], pal);
            LDSM4(bh[n], qh0); LDSM4(bh[n] + 4, qh1);
            LDSM4(bl[n], ql0); LDSM4(bl[n] + 4, ql1);
        }
#pragma unroll
        for (int ni = 0; ni < 4; ni++) mma16816(acc[ni], ah[c], bh[c] + ni * 2);
#pragma unroll
        for (int ni = 0; ni < 4; ni++) mma16816(acc[ni], ah[c], bl[c] + ni * 2);
#pragma unroll
        for (int ni = 0; ni < 4; ni++) mma16816(acc[ni], al[c], bh[c] + ni * 2);
    }
}

// Paired products sharing B: accY += Y@T, accZ += Z@T. Double-buffered;
// Y and Z chains interleaved -> dependent MMAs 8 apart.
__device__ __forceinline__ void mm_pair(const uint32_t* Yh, const uint32_t* Yl,
                                        const uint32_t* Zh, const uint32_t* Zl,
                                        const uint32_t* Th, const uint32_t* Tl,
                                        float accY[4][4], float accZ[4][4],
                                        int r0, int c0, int lane) {
    const uint32_t ao = a_off(r0, lane), bo = b_off(c0, lane);
    uint32_t pyh = sp(Yh) + ao, pyl = sp(Yl) + ao;
    uint32_t pzh = sp(Zh) + ao, pzl = sp(Zl) + ao;
    uint32_t qh0 = sp(Th) + bo, qh1 = qh0 + 16 * PITCHB;
    uint32_t ql0 = sp(Tl) + bo, ql1 = ql0 + 16 * PITCHB;
    uint32_t ayh[2][4], ayl[2][4], azh[2][4], azl[2][4], bh[2][8], bl[2][8];
    LDSM4(ayh[0], pyh); LDSM4(ayl[0], pyl);
    LDSM4(azh[0], pzh); LDSM4(azl[0], pzl);
    LDSM4(bh[0], qh0); LDSM4(bh[0] + 4, qh1);
    LDSM4(bl[0], ql0); LDSM4(bl[0] + 4, ql1);
#pragma unroll
    for (int k = 0; k < 8; k++) {
        const int c = k & 1, n = c ^ 1;
        if (k < 7) {
            pyh += 32; pyl += 32; pzh += 32; pzl += 32;
            qh0 += 32; qh1 += 32; ql0 += 32; ql1 += 32;
            LDSM4(ayh[n], pyh); LDSM4(ayl[n], pyl);
            LDSM4(azh[n], pzh); LDSM4(azl[n], pzl);
            LDSM4(bh[n], qh0); LDSM4(bh[n] + 4, qh1);
            LDSM4(bl[n], ql0); LDSM4(bl[n] + 4, ql1);
        }
#pragma unroll
        for (int ni = 0; ni < 4; ni++) mma16816(accY[ni], ayh[c], bh[c] + ni * 2);
#pragma unroll
        for (int ni = 0; ni < 4; ni++) mma16816(accZ[ni], azh[c], bh[c] + ni * 2);
#pragma unroll
        for (int ni = 0; ni < 4; ni++) mma16816(accY[ni], ayh[c], bl[c] + ni * 2);
#pragma unroll
        for (int ni = 0; ni < 4; ni++) mma16816(accZ[ni], azh[c], bl[c] + ni * 2);
#pragma unroll
        for (int ni = 0; ni < 4; ni++) mma16816(accY[ni], ayl[c], bh[c] + ni * 2);
#pragma unroll
        for (int ni = 0; ni < 4; ni++) mma16816(accZ[ni], azl[c], bh[c] + ni * 2);
    }
}

// v = alpha*acc + beta*I -> hi/lo pair; optional mirror to transposed pos.
__device__ __forceinline__ void epi_half(const float acc[4][4],
                                         uint32_t* __restrict__ Bh,
                                         uint32_t* __restrict__ Bl, float alpha,
                                         float beta, int r0, int c0, int lane,
                                         bool mir) {
    const int qr = lane >> 2, cp = (lane & 3) * 2;
    uint16_t* H16 = (uint16_t*)Bh;
    uint16_t* L16 = (uint16_t*)Bl;
#pragma unroll
    for (int ni = 0; ni < 4; ni++) {
        const int col = c0 + ni * 8 + cp;
#pragma unroll
        for (int h = 0; h < 2; h++) {
            const int row = r0 + qr + h * 8;
            float v0 = alpha * acc[ni][2 * h]     + ((row == col)     ? beta : 0.f);
            float v1 = alpha * acc[ni][2 * h + 1] + ((row == col + 1) ? beta : 0.f);
            uint32_t hw, lw;
            split2f(v0, v1, hw, lw);
            const int idx = row * PITCH32 + (col >> 1);
            Bh[idx] = hw;
            Bl[idx] = lw;
            if (mir) {
                H16[col * PITCH16 + row]       = (uint16_t)hw;
                H16[(col + 1) * PITCH16 + row] = (uint16_t)(hw >> 16);
                L16[col * PITCH16 + row]       = (uint16_t)lw;
                L16[(col + 1) * PITCH16 + row] = (uint16_t)(lw >> 16);
            }
        }
    }
}

__device__ __forceinline__ void epi_out_half(const float acc[4][4],
                                             float* __restrict__ Ob, float s,
                                             int r0, int c0, int lane) {
    const int qr = lane >> 2, cp = (lane & 3) * 2;
#pragma unroll
    for (int ni = 0; ni < 4; ni++) {
        const int col = c0 + ni * 8 + cp;
#pragma unroll
        for (int h = 0; h < 2; h++) {
            const int row = r0 + qr + h * 8;
            *(float2*)(Ob + row * 128 + col) =
                make_float2(s * acc[ni][2 * h], s * acc[ni][2 * h + 1]);
        }
    }
}

__device__ __constant__ int LTI[10] = {0, 1, 1, 2, 2, 2, 3, 3, 3, 3};
__device__ __constant__ int LTJ[10] = {0, 0, 1, 0, 1, 2, 0, 1, 2, 3};

__global__ void __launch_bounds__(NT, 1)
ns_ilp_kernel(const float* __restrict__ A, float* __restrict__ Out) {
    extern __shared__ uint32_t sm[];
    uint32_t* Yh = sm;
    uint32_t* Yl = sm + 128 * PITCH32;
    uint32_t* Zh = sm + 2 * 128 * PITCH32;
    uint32_t* Zl = sm + 3 * 128 * PITCH32;
    uint32_t* Th = sm + 4 * 128 * PITCH32;
    uint32_t* Tl = sm + 5 * 128 * PITCH32;
    __shared__ float red[12];

    const int tid = threadIdx.x, w = tid >> 5, lane = tid & 31;
    const float* Ab = A + (size_t)blockIdx.x * 16384;
    float* Ob = Out + (size_t)blockIdx.x * 16384;

    // --- Task geometry (20 triangular halves; task t: p=t%10, h=t/10) ---
    // Warp w owns tasks w and w+12 (if < 20). Per-SMSP: exactly 5 tasks.
    const int t0 = w;
    const int p0 = t0 % 10, h0 = t0 / 10;
    const int T0r = LTI[p0] * 32 + h0 * 16, T0c = LTJ[p0] * 32;
    const bool T0m = (LTI[p0] != LTJ[p0]);
    const bool has1 = (w < 8);
    const int t1 = w + 12;
    const int p1 = t1 % 10, h1 = t1 / 10;
    const int T1r = LTI[p1] * 32 + h1 * 16, T1c = LTJ[p1] * 32;
    const bool T1m = (LTI[p1] != LTJ[p1]);
    // Last full grid: 32 halves; warp w owns w, w+12, (w<8) w+24.
    const int La = w,      Lar = (La & 7) * 16,  Lac = (La >> 3) * 32;
    const int Lb = w + 12, Lbr = (Lb & 7) * 16,  Lbc = (Lb >> 3) * 32;
    const int Lc = w + 24, Lcr = (Lc & 7) * 16,  Lcc = (Lc >> 3) * 32;

    // ---- Frobenius norm ----
    float ss = 0.f;
    const float4* A4 = (const float4*)Ab;
    for (int i = tid; i < 4096; i += NT) {
        float4 v = A4[i];
        ss = fmaf(v.x, v.x, fmaf(v.y, v.y, fmaf(v.z, v.z, fmaf(v.w, v.w, ss))));
    }
#pragma unroll
    for (int o = 16; o; o >>= 1) ss += __shfl_xor_sync(0xffffffffu, ss, o);
    if (lane == 0) red[w] = ss;
    __syncthreads();
    float tot = 0.f;
#pragma unroll
    for (int i = 0; i < 12; i++) tot += red[i];
    const float normA = sqrtf(tot);
    const float inv = 1.f / normA;

    // ---- Init: Y0 = A*inv; T1 = Z1 = 1.5I - 0.5*Y0 (all split) ----
    for (int u = tid; u < 2048; u += NT) {
        const int row = u >> 4;
        const int col = (u & 15) * 8;
        float4 a0 = *(const float4*)(Ab + row * 128 + col);
        float4 a1 = *(const float4*)(Ab + row * 128 + col + 4);
        float yv[8] = {a0.x * inv, a0.y * inv, a0.z * inv, a0.w * inv,
                       a1.x * inv, a1.y * inv, a1.z * inv, a1.w * inv};
#pragma unroll
        for (int jj = 0; jj < 4; jj++) {
            const int cc = col + 2 * jj;
            const int idx = row * PITCH32 + (cc >> 1);
            uint32_t hw, lw;
            split2f(yv[2 * jj], yv[2 * jj + 1], hw, lw);
            Yh[idx] = hw; Yl[idx] = lw;
            float q0 = -0.5f * yv[2 * jj]     + (row == cc     ? 1.5f : 0.f);
            float q1 = -0.5f * yv[2 * jj + 1] + (row == cc + 1 ? 1.5f : 0.f);
            split2f(q0, q1, hw, lw);
            Th[idx] = hw; Tl[idx] = lw;
            Zh[idx] = hw; Zl[idx] = lw;
        }
    }
    __syncthreads();

    // ---- iter 1 (reduced): Y = Y @ T1, triangular ----
    {
        float a0[4][4], a1[4][4];
        zero4(a0);
        mm_half(Yh, Yl, Th, Tl, a0, T0r, T0c, lane);
        if (has1) {
            zero4(a1);
            mm_half(Yh, Yl, Th, Tl, a1, T1r, T1c, lane);
        }
        __syncthreads();
        epi_half(a0, Yh, Yl, 1.f, 0.f, T0r, T0c, lane, T0m);
        if (has1) epi_half(a1, Yh, Yl, 1.f, 0.f, T1r, T1c, lane, T1m);
        __syncthreads();
    }

    // ---- iters 2..5 ----
#pragma unroll 1
    for (int it = 1; it < 5; ++it) {
        // P1: T = 1.5I - 0.5*(Z @ Y); epilogue fused (T not a P1 operand)
        {
            float a0[4][4];
            zero4(a0);
            mm_half(Zh, Zl, Yh, Yl, a0, T0r, T0c, lane);
            epi_half(a0, Th, Tl, -0.5f, 1.5f, T0r, T0c, lane, T0m);
            if (has1) {
                zero4(a0);
                mm_half(Zh, Zl, Yh, Yl, a0, T1r, T1c, lane);
                epi_half(a0, Th, Tl, -0.5f, 1.5f, T1r, T1c, lane, T1m);
            }
        }
        __syncthreads();

        if (it < 4) {
            // P2: Y = Y@T and Z = Z@T as paired tasks (shared B fragments)
            float ay0[4][4], az0[4][4];
            zero4(ay0); zero4(az0);
            mm_pair(Yh, Yl, Zh, Zl, Th, Tl, ay0, az0, T0r, T0c, lane);
            float ay1[4][4], az1[4][4];
            if (has1) {
                zero4(ay1); zero4(az1);
                mm_pair(Yh, Yl, Zh, Zl, Th, Tl, ay1, az1, T1r, T1c, lane);
            }
            __syncthreads();
            epi_half(ay0, Yh, Yl, 1.f, 0.f, T0r, T0c, lane, T0m);
            epi_half(az0, Zh, Zl, 1.f, 0.f, T0r, T0c, lane, T0m);
            if (has1) {
                epi_half(ay1, Yh, Yl, 1.f, 0.f, T1r, T1c, lane, T1m);
                epi_half(az1, Zh, Zl, 1.f, 0.f, T1r, T1c, lane, T1m);
            }
            __syncthreads();
        } else {
            // Last: Y5 = Y@T full grid, straight to GMEM
            const float s = sqrtf(normA);
            float a0[4][4];
            zero4(a0);
            mm_half(Yh, Yl, Th, Tl, a0, Lar, Lac, lane);
            epi_out_half(a0, Ob, s, Lar, Lac, lane);
            zero4(a0);
            mm_half(Yh, Yl, Th, Tl, a0, Lbr, Lbc, lane);
            epi_out_half(a0, Ob, s, Lbr, Lbc, lane);
            if (w < 8) {
                zero4(a0);
                mm_half(Yh, Yl, Th, Tl, a0, Lcr, Lcc, lane);
                epi_out_half(a0, Ob, s, Lcr, Lcc, lane);
            }
        }
    }
}

extern "C" void kernel_launch(void* const* d_in, const int* in_sizes, int n_in,
                              void* d_out, int out_size) {
    const float* A = (const float*)d_in[0];
    float* out = (float*)d_out;
    const int nbatch = in_sizes[0] / (NMAT * NMAT);            // 1024
    const size_t smem = 6 * 128 * PITCH32 * sizeof(uint32_t);  // 208896 B
    cudaFuncSetAttribute(ns_ilp_kernel,
                         cudaFuncAttributeMaxDynamicSharedMemorySize, (int)smem);
    ns_ilp_kernel<<<nbatch, NT, smem>>>(A, out);
}

// round 11
// speedup vs baseline: 1.4789x; 1.0068x over previous
#include <cuda_runtime.h>
#include <cuda_bf16.h>
#include <cstdint>

// Batched Newton-Schulz matrix sqrt: 1024 x (128x128 fp32), 5 iterations.
// mma.sync bf16 + ldmatrix, fp32 via hi+lo split (hh+hl+lh), triangular
// outputs + mirror. 16 warps (4/SMSP), mixed n32/n16 task granularity for
// exact per-warp balance; P2 pairs Y@T with Z@T sharing B fragments.

#define NMAT 128
#define NT 512
#define PITCH32 68      // u32 words per smem row
#define PITCHB 272      // bytes per smem row
#define PITCH16 136

__device__ __forceinline__ void mma16816(float* d, const uint32_t* a,
                                         const uint32_t* b) {
    asm volatile(
        "mma.sync.aligned.m16n8k16.row.col.f32.bf16.bf16.f32 "
        "{%0,%1,%2,%3}, {%4,%5,%6,%7}, {%8,%9}, {%0,%1,%2,%3};"
        : "+f"(d[0]), "+f"(d[1]), "+f"(d[2]), "+f"(d[3])
        : "r"(a[0]), "r"(a[1]), "r"(a[2]), "r"(a[3]), "r"(b[0]), "r"(b[1]));
}

#define LDSM4(r_, a_)                                                         \
    asm volatile("ldmatrix.sync.aligned.m8n8.x4.shared.b16 {%0,%1,%2,%3}, [%4];" \
                 : "=r"((r_)[0]), "=r"((r_)[1]), "=r"((r_)[2]), "=r"((r_)[3])  \
                 : "r"(a_))

__device__ __forceinline__ uint32_t sp(const void* p) {
    return (uint32_t)__cvta_generic_to_shared(p);
}

__device__ __forceinline__ void split2f(float v0, float v1, uint32_t& hw,
                                        uint32_t& lw) {
    asm("cvt.rn.bf16x2.f32 %0, %1, %2;" : "=r"(hw) : "f"(v1), "f"(v0));
    float h0 = __uint_as_float(hw << 16);
    float h1 = __uint_as_float(hw & 0xffff0000u);
    float l0 = v0 - h0, l1 = v1 - h1;
    asm("cvt.rn.bf16x2.f32 %0, %1, %2;" : "=r"(lw) : "f"(l1), "f"(l0));
}

__device__ __forceinline__ void zero4(float a[4][4]) {
#pragma unroll
    for (int i = 0; i < 4; i++)
#pragma unroll
        for (int j = 0; j < 4; j++) a[i][j] = 0.f;
}
__device__ __forceinline__ void zero2(float a[2][4]) {
#pragma unroll
    for (int i = 0; i < 2; i++)
#pragma unroll
        for (int j = 0; j < 4; j++) a[i][j] = 0.f;
}

// ldmatrix octet addressing
__device__ __forceinline__ uint32_t a_off(int r0, int lane) {
    return (uint32_t)((r0 + (lane & 7) + ((lane >> 3) & 1) * 8) * PITCHB +
                      (lane >> 4) * 16);
}
__device__ __forceinline__ uint32_t b_off(int c0, int lane) {
    return (uint32_t)((c0 + (lane & 7) + (lane >> 4) * 8) * PITCHB +
                      ((lane >> 3) & 1) * 16);
}

// n32 single product acc += Ph@Qh + Ph@Ql + Pl@Qh (double-buffered).
__device__ __forceinline__ void mm_half(const uint32_t* Ph, const uint32_t* Pl,
                                        const uint32_t* Qh, const uint32_t* Ql,
                                        float acc[4][4], int r0, int c0,
                                        int lane) {
    const uint32_t ao = a_off(r0, lane), bo = b_off(c0, lane);
    uint32_t pah = sp(Ph) + ao, pal = sp(Pl) + ao;
    uint32_t qh0 = sp(Qh) + bo, qh1 = qh0 + 16 * PITCHB;
    uint32_t ql0 = sp(Ql) + bo, ql1 = ql0 + 16 * PITCHB;
    uint32_t ah[2][4], al[2][4], bh[2][8], bl[2][8];
    LDSM4(ah[0], pah); LDSM4(al[0], pal);
    LDSM4(bh[0], qh0); LDSM4(bh[0] + 4, qh1);
    LDSM4(bl[0], ql0); LDSM4(bl[0] + 4, ql1);
#pragma unroll
    for (int k = 0; k < 8; k++) {
        const int c = k & 1, n = c ^ 1;
        if (k < 7) {
            pah += 32; pal += 32; qh0 += 32; qh1 += 32; ql0 += 32; ql1 += 32;
            LDSM4(ah[n], pah); LDSM4(al[n], pal);
            LDSM4(bh[n], qh0); LDSM4(bh[n] + 4, qh1);
            LDSM4(bl[n], ql0); LDSM4(bl[n] + 4, ql1);
        }
#pragma unroll
        for (int ni = 0; ni < 4; ni++) {
            mma16816(acc[ni], ah[c], bh[c] + ni * 2);
            mma16816(acc[ni], ah[c], bl[c] + ni * 2);
            mma16816(acc[ni], al[c], bh[c] + ni * 2);
        }
    }
}

// n16 single product (quarter): acc[2][4]
__device__ __forceinline__ void mm_q(const uint32_t* Ph, const uint32_t* Pl,
                                     const uint32_t* Qh, const uint32_t* Ql,
                                     float acc[2][4], int r0, int c0, int lane) {
    const uint32_t ao = a_off(r0, lane), bo = b_off(c0, lane);
    uint32_t pah = sp(Ph) + ao, pal = sp(Pl) + ao;
    uint32_t qh0 = sp(Qh) + bo, ql0 = sp(Ql) + bo;
#pragma unroll
    for (int k = 0; k < 8; k++) {
        uint32_t ah[4], al[4], bh[4], bl[4];
        LDSM4(ah, pah); LDSM4(al, pal);
        LDSM4(bh, qh0); LDSM4(bl, ql0);
        pah += 32; pal += 32; qh0 += 32; ql0 += 32;
#pragma unroll
        for (int ni = 0; ni < 2; ni++) {
            mma16816(acc[ni], ah, bh + ni * 2);
            mma16816(acc[ni], ah, bl + ni * 2);
            mma16816(acc[ni], al, bh + ni * 2);
        }
    }
}

// n32 paired: accY += Y@T, accZ += Z@T (shared B). Single-buffered.
__device__ __forceinline__ void mm_pair(const uint32_t* Yh, const uint32_t* Yl,
                                        const uint32_t* Zh, const uint32_t* Zl,
                                        const uint32_t* Th, const uint32_t* Tl,
                                        float accY[4][4], float accZ[4][4],
                                        int r0, int c0, int lane) {
    const uint32_t ao = a_off(r0, lane), bo = b_off(c0, lane);
    uint32_t pyh = sp(Yh) + ao, pyl = sp(Yl) + ao;
    uint32_t pzh = sp(Zh) + ao, pzl = sp(Zl) + ao;
    uint32_t qh0 = sp(Th) + bo, qh1 = qh0 + 16 * PITCHB;
    uint32_t ql0 = sp(Tl) + bo, ql1 = ql0 + 16 * PITCHB;
#pragma unroll
    for (int k = 0; k < 8; k++) {
        uint32_t ayh[4], ayl[4], azh[4], azl[4], bh[8], bl[8];
        LDSM4(ayh, pyh); LDSM4(ayl, pyl);
        LDSM4(azh, pzh); LDSM4(azl, pzl);
        LDSM4(bh, qh0); LDSM4(bh + 4, qh1);
        LDSM4(bl, ql0); LDSM4(bl + 4, ql1);
        pyh += 32; pyl += 32; pzh += 32; pzl += 32;
        qh0 += 32; qh1 += 32; ql0 += 32; ql1 += 32;
#pragma unroll
        for (int ni = 0; ni < 4; ni++) {
            mma16816(accY[ni], ayh, bh + ni * 2);
            mma16816(accY[ni], ayh, bl + ni * 2);
            mma16816(accY[ni], ayl, bh + ni * 2);
            mma16816(accZ[ni], azh, bh + ni * 2);
            mma16816(accZ[ni], azh, bl + ni * 2);
            mma16816(accZ[ni], azl, bh + ni * 2);
        }
    }
}

// v = alpha*acc + beta*I -> hi/lo pair; optional mirror (NI = 4 or 2)
template <int NI>
__device__ __forceinline__ void epi_t(const float acc[NI][4],
                                      uint32_t* __restrict__ Bh,
                                      uint32_t* __restrict__ Bl, float alpha,
                                      float beta, int r0, int c0, int lane,
                                      bool mir) {
    const int qr = lane >> 2, cp = (lane & 3) * 2;
    uint16_t* H16 = (uint16_t*)Bh;
    uint16_t* L16 = (uint16_t*)Bl;
#pragma unroll
    for (int ni = 0; ni < NI; ni++) {
        const int col = c0 + ni * 8 + cp;
#pragma unroll
        for (int h = 0; h < 2; h++) {
            const int row = r0 + qr + h * 8;
            float v0 = alpha * acc[ni][2 * h]     + ((row == col)     ? beta : 0.f);
            float v1 = alpha * acc[ni][2 * h + 1] + ((row == col + 1) ? beta : 0.f);
            uint32_t hw, lw;
            split2f(v0, v1, hw, lw);
            const int idx = row * PITCH32 + (col >> 1);
            Bh[idx] = hw;
            Bl[idx] = lw;
            if (mir) {
                H16[col * PITCH16 + row]       = (uint16_t)hw;
                H16[(col + 1) * PITCH16 + row] = (uint16_t)(hw >> 16);
                L16[col * PITCH16 + row]       = (uint16_t)lw;
                L16[(col + 1) * PITCH16 + row] = (uint16_t)(lw >> 16);
            }
        }
    }
}

template <int NI>
__device__ __forceinline__ void epi_out_t(const float acc[NI][4],
                                          float* __restrict__ Ob, float s,
                                          int r0, int c0, int lane) {
    const int qr = lane >> 2, cp = (lane & 3) * 2;
#pragma unroll
    for (int ni = 0; ni < NI; ni++) {
        const int col = c0 + ni * 8 + cp;
#pragma unroll
        for (int h = 0; h < 2; h++) {
            const int row = r0 + qr + h * 8;
            *(float2*)(Ob + row * 128 + col) =
                make_float2(s * acc[ni][2 * h], s * acc[ni][2 * h + 1]);
        }
    }
}

__device__ __constant__ int LTI[10] = {0, 1, 1, 2, 2, 2, 3, 3, 3, 3};
__device__ __constant__ int LTJ[10] = {0, 0, 1, 0, 1, 2, 0, 1, 2, 3};

__global__ void __launch_bounds__(NT, 1)
ns_bal_kernel(const float* __restrict__ A, float* __restrict__ Out) {
    extern __shared__ uint32_t sm[];
    uint32_t* Yh = sm;
    uint32_t* Yl = sm + 128 * PITCH32;
    uint32_t* Zh = sm + 2 * 128 * PITCH32;
    uint32_t* Zl = sm + 3 * 128 * PITCH32;
    uint32_t* Th = sm + 4 * 128 * PITCH32;
    uint32_t* Tl = sm + 5 * 128 * PITCH32;
    __shared__ float red[16];

    const int tid = threadIdx.x, w = tid >> 5, lane = tid & 31;
    const float* Ab = A + (size_t)blockIdx.x * 16384;
    float* Ob = Out + (size_t)blockIdx.x * 16384;

    // --- Task geometry ---
    // 20 half-positions (m16n32): t: p=t%10, h=t/10. Warps 0-15 own t=w.
    const int p0 = w % 10, h0 = w / 10;
    const int Hr = LTI[p0] * 32 + h0 * 16, Hc = LTJ[p0] * 32;
    const bool Hm = (LTI[p0] != LTJ[p0]);
    // Quarter tasks from half-positions 16-19 (p=6..9, h=1), split n16:
    // qi = w&7 -> position 16+(qi>>1), quarter (qi&1).
    const int qi = w & 7;
    const int qp = 6 + (qi >> 1);
    const int Qr = LTI[qp] * 32 + 16;
    const int Qc = LTJ[qp] * 32 + (qi & 1) * 16;
    const bool Qm = (LTI[qp] != LTJ[qp]);
    const bool p1q = (w >= 8);   // P1: warps 8-15 also run the quarter task
    // Last full iter: 64 n16 quarters; warp w owns u = w,w+16,w+32,w+48:
    // u -> r=(u&7)*16, c=(u>>3)*16.

    // ---- Frobenius norm ----
    float ss = 0.f;
    const float4* A4 = (const float4*)Ab;
    for (int i = tid; i < 4096; i += NT) {
        float4 v = A4[i];
        ss = fmaf(v.x, v.x, fmaf(v.y, v.y, fmaf(v.z, v.z, fmaf(v.w, v.w, ss))));
    }
#pragma unroll
    for (int o = 16; o; o >>= 1) ss += __shfl_xor_sync(0xffffffffu, ss, o);
    if (lane == 0) red[w] = ss;
    __syncthreads();
    float tot = 0.f;
#pragma unroll
    for (int i = 0; i < 16; i++) tot += red[i];
    const float normA = sqrtf(tot);
    const float inv = 1.f / normA;

    // ---- Init: Y0 = A*inv; T1 = Z1 = 1.5I - 0.5*Y0 (all split) ----
    for (int u = tid; u < 2048; u += NT) {
        const int row = u >> 4;
        const int col = (u & 15) * 8;
        float4 a0 = *(const float4*)(Ab + row * 128 + col);
        float4 a1 = *(const float4*)(Ab + row * 128 + col + 4);
        float yv[8] = {a0.x * inv, a0.y * inv, a0.z * inv, a0.w * inv,
                       a1.x * inv, a1.y * inv, a1.z * inv, a1.w * inv};
#pragma unroll
        for (int jj = 0; jj < 4; jj++) {
            const int cc = col + 2 * jj;
            const int idx = row * PITCH32 + (cc >> 1);
            uint32_t hw, lw;
            split2f(yv[2 * jj], yv[2 * jj + 1], hw, lw);
            Yh[idx] = hw; Yl[idx] = lw;
            float q0 = -0.5f * yv[2 * jj]     + (row == cc     ? 1.5f : 0.f);
            float q1 = -0.5f * yv[2 * jj + 1] + (row == cc + 1 ? 1.5f : 0.f);
            split2f(q0, q1, hw, lw);
            Th[idx] = hw; Tl[idx] = lw;
            Zh[idx] = hw; Zl[idx] = lw;
        }
    }
    __syncthreads();

    // ---- iter 1 (reduced): Y = Y @ T1, triangular ----
    {
        float ah[4][4];
        float aq[2][4];
        zero4(ah);
        mm_half(Yh, Yl, Th, Tl, ah, Hr, Hc, lane);
        if (p1q) {
            zero2(aq);
            mm_q(Yh, Yl, Th, Tl, aq, Qr, Qc, lane);
        }
        __syncthreads();
        epi_t<4>(ah, Yh, Yl, 1.f, 0.f, Hr, Hc, lane, Hm);
        if (p1q) epi_t<2>(aq, Yh, Yl, 1.f, 0.f, Qr, Qc, lane, Qm);
        __syncthreads();
    }

    // ---- iters 2..5 ----
#pragma unroll 1
    for (int it = 1; it < 5; ++it) {
        // P1: T = 1.5I - 0.5*(Z @ Y); epilogue fused (T not a P1 operand)
        {
            float ah[4][4];
            zero4(ah);
            mm_half(Zh, Zl, Yh, Yl, ah, Hr, Hc, lane);
            epi_t<4>(ah, Th, Tl, -0.5f, 1.5f, Hr, Hc, lane, Hm);
            if (p1q) {
                float aq[2][4];
                zero2(aq);
                mm_q(Zh, Zl, Yh, Yl, aq, Qr, Qc, lane);
                epi_t<2>(aq, Th, Tl, -0.5f, 1.5f, Qr, Qc, lane, Qm);
            }
        }
        __syncthreads();

        if (it < 4) {
            // P2: each warp = 1 n32 pair (Y&Z, shared B) + 1 n16 single
            float ay[4][4], az[4][4], aq[2][4];
            zero4(ay); zero4(az);
            mm_pair(Yh, Yl, Zh, Zl, Th, Tl, ay, az, Hr, Hc, lane);
            zero2(aq);
            if (w < 8) mm_q(Yh, Yl, Th, Tl, aq, Qr, Qc, lane);
            else       mm_q(Zh, Zl, Th, Tl, aq, Qr, Qc, lane);
            __syncthreads();
            epi_t<4>(ay, Yh, Yl, 1.f, 0.f, Hr, Hc, lane, Hm);
            epi_t<4>(az, Zh, Zl, 1.f, 0.f, Hr, Hc, lane, Hm);
            if (w < 8) epi_t<2>(aq, Yh, Yl, 1.f, 0.f, Qr, Qc, lane, Qm);
            else       epi_t<2>(aq, Zh, Zl, 1.f, 0.f, Qr, Qc, lane, Qm);
            __syncthreads();
        } else {
            // Last: Y5 = Y@T full grid (64 n16 quarters), straight to GMEM
            const float s = sqrtf(normA);
#pragma unroll
            for (int j = 0; j < 4; j++) {
                const int u = w + j * 16;
                const int r = (u & 7) * 16, c = (u >> 3) * 16;
                float aq[2][4];
                zero2(aq);
                mm_q(Yh, Yl, Th, Tl, aq, r, c, lane);
                epi_out_t<2>(aq, Ob, s, r, c, lane);
            }
        }
    }
}

extern "C" void kernel_launch(void* const* d_in, const int* in_sizes, int n_in,
                              void* d_out, int out_size) {
    const float* A = (const float*)d_in[0];
    float* out = (float*)d_out;
    const int nbatch = in_sizes[0] / (NMAT * NMAT);            // 1024
    const size_t smem = 6 * 128 * PITCH32 * sizeof(uint32_t);  // 208896 B
    cudaFuncSetAttribute(ns_bal_kernel,
                         cudaFuncAttributeMaxDynamicSharedMemorySize, (int)smem);
    ns_bal_kernel<<<nbatch, NT, smem>>>(A, out);
}

// round 12
// speedup vs baseline: 1.5621x; 1.0563x over previous
#include <cuda_runtime.h>
#include <cuda_bf16.h>
#include <cstdint>

// Batched Newton-Schulz matrix sqrt: 1024 x (128x128 fp32), 5 iterations.
// mma.sync bf16 + ldmatrix, fp32 via hi+lo split (hh+hl+lh), triangular
// outputs + mirror. 16 warps; m32n32 single-product tasks amortize the
// B-fragment smem reads (171 B/MMA) with only 32 accumulator registers.

#define NMAT 128
#define NT 512
#define PITCH32 68      // u32 words per smem row
#define PITCHB 272      // bytes per smem row
#define PITCH16 136

__device__ __forceinline__ void mma16816(float* d, const uint32_t* a,
                                         const uint32_t* b) {
    asm volatile(
        "mma.sync.aligned.m16n8k16.row.col.f32.bf16.bf16.f32 "
        "{%0,%1,%2,%3}, {%4,%5,%6,%7}, {%8,%9}, {%0,%1,%2,%3};"
        : "+f"(d[0]), "+f"(d[1]), "+f"(d[2]), "+f"(d[3])
        : "r"(a[0]), "r"(a[1]), "r"(a[2]), "r"(a[3]), "r"(b[0]), "r"(b[1]));
}

#define LDSM4(r_, a_)                                                         \
    asm volatile("ldmatrix.sync.aligned.m8n8.x4.shared.b16 {%0,%1,%2,%3}, [%4];" \
                 : "=r"((r_)[0]), "=r"((r_)[1]), "=r"((r_)[2]), "=r"((r_)[3])  \
                 : "r"(a_))

__device__ __forceinline__ uint32_t sp(const void* p) {
    return (uint32_t)__cvta_generic_to_shared(p);
}

__device__ __forceinline__ void split2f(float v0, float v1, uint32_t& hw,
                                        uint32_t& lw) {
    asm("cvt.rn.bf16x2.f32 %0, %1, %2;" : "=r"(hw) : "f"(v1), "f"(v0));
    float h0 = __uint_as_float(hw << 16);
    float h1 = __uint_as_float(hw & 0xffff0000u);
    float l0 = v0 - h0, l1 = v1 - h1;
    asm("cvt.rn.bf16x2.f32 %0, %1, %2;" : "=r"(lw) : "f"(l1), "f"(l0));
}

__device__ __forceinline__ void zero4(float a[4][4]) {
#pragma unroll
    for (int i = 0; i < 4; i++)
#pragma unroll
        for (int j = 0; j < 4; j++) a[i][j] = 0.f;
}

// ldmatrix octet addressing
__device__ __forceinline__ uint32_t a_off(int r0, int lane) {
    return (uint32_t)((r0 + (lane & 7) + ((lane >> 3) & 1) * 8) * PITCHB +
                      (lane >> 4) * 16);
}
__device__ __forceinline__ uint32_t b_off(int c0, int lane) {
    return (uint32_t)((c0 + (lane & 7) + (lane >> 4) * 8) * PITCHB +
                      ((lane >> 3) & 1) * 16);
}

// m16n32 single product (double-buffered): acc += Ph@Qh + Ph@Ql + Pl@Qh
__device__ __forceinline__ void mm_half(const uint32_t* Ph, const uint32_t* Pl,
                                        const uint32_t* Qh, const uint32_t* Ql,
                                        float acc[4][4], int r0, int c0,
                                        int lane) {
    const uint32_t ao = a_off(r0, lane), bo = b_off(c0, lane);
    uint32_t pah = sp(Ph) + ao, pal = sp(Pl) + ao;
    uint32_t qh0 = sp(Qh) + bo, qh1 = qh0 + 16 * PITCHB;
    uint32_t ql0 = sp(Ql) + bo, ql1 = ql0 + 16 * PITCHB;
    uint32_t ah[2][4], al[2][4], bh[2][8], bl[2][8];
    LDSM4(ah[0], pah); LDSM4(al[0], pal);
    LDSM4(bh[0], qh0); LDSM4(bh[0] + 4, qh1);
    LDSM4(bl[0], ql0); LDSM4(bl[0] + 4, ql1);
#pragma unroll
    for (int k = 0; k < 8; k++) {
        const int c = k & 1, n = c ^ 1;
        if (k < 7) {
            pah += 32; pal += 32; qh0 += 32; qh1 += 32; ql0 += 32; ql1 += 32;
            LDSM4(ah[n], pah); LDSM4(al[n], pal);
            LDSM4(bh[n], qh0); LDSM4(bh[n] + 4, qh1);
            LDSM4(bl[n], ql0); LDSM4(bl[n] + 4, ql1);
        }
#pragma unroll
        for (int ni = 0; ni < 4; ni++) {
            mma16816(acc[ni], ah[c], bh[c] + ni * 2);
            mma16816(acc[ni], ah[c], bl[c] + ni * 2);
            mma16816(acc[ni], al[c], bh[c] + ni * 2);
        }
    }
}

// m32n32 single product (B amortized over 32 rows, single-buffered)
__device__ __forceinline__ void mm32(const uint32_t* Ph, const uint32_t* Pl,
                                     const uint32_t* Qh, const uint32_t* Ql,
                                     float acc[2][4][4], int r0, int c0,
                                     int lane) {
    const uint32_t ao0 = a_off(r0, lane), ao1 = a_off(r0 + 16, lane);
    const uint32_t bo = b_off(c0, lane);
    uint32_t ph0 = sp(Ph) + ao0, ph1 = sp(Ph) + ao1;
    uint32_t pl0 = sp(Pl) + ao0, pl1 = sp(Pl) + ao1;
    uint32_t qh0 = sp(Qh) + bo, qh1 = qh0 + 16 * PITCHB;
    uint32_t ql0 = sp(Ql) + bo, ql1 = ql0 + 16 * PITCHB;
#pragma unroll
    for (int k = 0; k < 8; k++) {
        uint32_t ah[2][4], al[2][4], bh[8], bl[8];
        LDSM4(ah[0], ph0); LDSM4(ah[1], ph1);
        LDSM4(al[0], pl0); LDSM4(al[1], pl1);
        LDSM4(bh, qh0); LDSM4(bh + 4, qh1);
        LDSM4(bl, ql0); LDSM4(bl + 4, ql1);
        ph0 += 32; ph1 += 32; pl0 += 32; pl1 += 32;
        qh0 += 32; qh1 += 32; ql0 += 32; ql1 += 32;
#pragma unroll
        for (int ni = 0; ni < 4; ni++) {
            mma16816(acc[0][ni], ah[0], bh + ni * 2);
            mma16816(acc[1][ni], ah[1], bh + ni * 2);
            mma16816(acc[0][ni], ah[0], bl + ni * 2);
            mma16816(acc[1][ni], ah[1], bl + ni * 2);
            mma16816(acc[0][ni], al[0], bh + ni * 2);
            mma16816(acc[1][ni], al[1], bh + ni * 2);
        }
    }
}

// v = alpha*acc + beta*I -> hi/lo pair; optional mirror to transposed pos.
__device__ __forceinline__ void epi_half(const float acc[4][4],
                                         uint32_t* __restrict__ Bh,
                                         uint32_t* __restrict__ Bl, float alpha,
                                         float beta, int r0, int c0, int lane,
                                         bool mir) {
    const int qr = lane >> 2, cp = (lane & 3) * 2;
    uint16_t* H16 = (uint16_t*)Bh;
    uint16_t* L16 = (uint16_t*)Bl;
#pragma unroll
    for (int ni = 0; ni < 4; ni++) {
        const int col = c0 + ni * 8 + cp;
#pragma unroll
        for (int h = 0; h < 2; h++) {
            const int row = r0 + qr + h * 8;
            float v0 = alpha * acc[ni][2 * h]     + ((row == col)     ? beta : 0.f);
            float v1 = alpha * acc[ni][2 * h + 1] + ((row == col + 1) ? beta : 0.f);
            uint32_t hw, lw;
            split2f(v0, v1, hw, lw);
            const int idx = row * PITCH32 + (col >> 1);
            Bh[idx] = hw;
            Bl[idx] = lw;
            if (mir) {
                H16[col * PITCH16 + row]       = (uint16_t)hw;
                H16[(col + 1) * PITCH16 + row] = (uint16_t)(hw >> 16);
                L16[col * PITCH16 + row]       = (uint16_t)lw;
                L16[(col + 1) * PITCH16 + row] = (uint16_t)(lw >> 16);
            }
        }
    }
}

__device__ __forceinline__ void epi_out_half(const float acc[4][4],
                                             float* __restrict__ Ob, float s,
                                             int r0, int c0, int lane) {
    const int qr = lane >> 2, cp = (lane & 3) * 2;
#pragma unroll
    for (int ni = 0; ni < 4; ni++) {
        const int col = c0 + ni * 8 + cp;
#pragma unroll
        for (int h = 0; h < 2; h++) {
            const int row = r0 + qr + h * 8;
            *(float2*)(Ob + row * 128 + col) =
                make_float2(s * acc[ni][2 * h], s * acc[ni][2 * h + 1]);
        }
    }
}

__device__ __constant__ int LTI[10] = {0, 1, 1, 2, 2, 2, 3, 3, 3, 3};
__device__ __constant__ int LTJ[10] = {0, 0, 1, 0, 1, 2, 0, 1, 2, 3};

__global__ void __launch_bounds__(NT, 1)
ns_m32_kernel(const float* __restrict__ A, float* __restrict__ Out) {
    extern __shared__ uint32_t sm[];
    uint32_t* Yh = sm;
    uint32_t* Yl = sm + 128 * PITCH32;
    uint32_t* Zh = sm + 2 * 128 * PITCH32;
    uint32_t* Zl = sm + 3 * 128 * PITCH32;
    uint32_t* Th = sm + 4 * 128 * PITCH32;
    uint32_t* Tl = sm + 5 * 128 * PITCH32;
    __shared__ float red[16];

    const int tid = threadIdx.x, w = tid >> 5, lane = tid & 31;
    const float* Ab = A + (size_t)blockIdx.x * 16384;
    float* Ob = Out + (size_t)blockIdx.x * 16384;

    // --- P1 / iter1 geometry ---
    // warps 0-7: m32 tiles 0-7 (2/SMSP); warps 8-11: m16 halves of tiles
    // 8 ((3,2)) and 9 ((3,3)) (1/SMSP); warps 12-15 idle in P1.
    const bool pbig = (w < 8);
    const bool p1act = (w < 12);
    const int p1t = pbig ? w : (8 + ((w - 8) >> 1));
    const int P1r = LTI[p1t] * 32 + (pbig ? 0 : ((w - 8) & 1) * 16);
    const int P1c = LTJ[p1t] * 32;
    const bool P1m = (LTI[p1t] != LTJ[p1t]);
    // --- P2 geometry: 20 m32 tasks (Y tiles 0-9, Z tiles 0-9) ---
    const bool z2a = (w >= 10);
    const int t2a = z2a ? (w - 10) : w;
    const int P2ar = LTI[t2a] * 32, P2ac = LTJ[t2a] * 32;
    const bool P2am = (LTI[t2a] != LTJ[t2a]);
    const bool has2b = (w < 4);
    const int t2b = w + 6;  // tasks 16-19 -> Z tiles 6-9
    const int P2br = LTI[t2b] * 32, P2bc = LTJ[t2b] * 32;
    const bool P2bm = (LTI[t2b] != LTJ[t2b]);
    // --- last iter: 16 full m32 tiles, warp w -> tile w ---
    const int Lr = (w & 3) * 32, Lc = (w >> 2) * 32;

    // ---- Frobenius norm ----
    float ss = 0.f;
    const float4* A4 = (const float4*)Ab;
    for (int i = tid; i < 4096; i += NT) {
        float4 v = A4[i];
        ss = fmaf(v.x, v.x, fmaf(v.y, v.y, fmaf(v.z, v.z, fmaf(v.w, v.w, ss))));
    }
#pragma unroll
    for (int o = 16; o; o >>= 1) ss += __shfl_xor_sync(0xffffffffu, ss, o);
    if (lane == 0) red[w] = ss;
    __syncthreads();
    float tot = 0.f;
#pragma unroll
    for (int i = 0; i < 16; i++) tot += red[i];
    const float normA = sqrtf(tot);
    const float inv = 1.f / normA;

    // ---- Init: Y0 = A*inv; T1 = Z1 = 1.5I - 0.5*Y0 (all split) ----
    for (int u = tid; u < 2048; u += NT) {
        const int row = u >> 4;
        const int col = (u & 15) * 8;
        float4 a0 = *(const float4*)(Ab + row * 128 + col);
        float4 a1 = *(const float4*)(Ab + row * 128 + col + 4);
        float yv[8] = {a0.x * inv, a0.y * inv, a0.z * inv, a0.w * inv,
                       a1.x * inv, a1.y * inv, a1.z * inv, a1.w * inv};
#pragma unroll
        for (int jj = 0; jj < 4; jj++) {
            const int cc = col + 2 * jj;
            const int idx = row * PITCH32 + (cc >> 1);
            uint32_t hw, lw;
            split2f(yv[2 * jj], yv[2 * jj + 1], hw, lw);
            Yh[idx] = hw; Yl[idx] = lw;
            float q0 = -0.5f * yv[2 * jj]     + (row == cc     ? 1.5f : 0.f);
            float q1 = -0.5f * yv[2 * jj + 1] + (row == cc + 1 ? 1.5f : 0.f);
            split2f(q0, q1, hw, lw);
            Th[idx] = hw; Tl[idx] = lw;
            Zh[idx] = hw; Zl[idx] = lw;
        }
    }
    __syncthreads();

    float acc[2][4][4];

    // ---- iter 1 (reduced): Y = Y @ T1, triangular ----
    {
        zero4(acc[0]); zero4(acc[1]);
        if (pbig)       mm32(Yh, Yl, Th, Tl, acc, P1r, P1c, lane);
        else if (p1act) mm_half(Yh, Yl, Th, Tl, acc[0], P1r, P1c, lane);
        __syncthreads();
        if (p1act) {
            epi_half(acc[0], Yh, Yl, 1.f, 0.f, P1r, P1c, lane, P1m);
            if (pbig)
                epi_half(acc[1], Yh, Yl, 1.f, 0.f, P1r + 16, P1c, lane, P1m);
        }
        __syncthreads();
    }

    // ---- iters 2..5 ----
#pragma unroll 1
    for (int it = 1; it < 5; ++it) {
        // P1: T = 1.5I - 0.5*(Z @ Y); epilogue fused (T not a P1 operand)
        {
            zero4(acc[0]); zero4(acc[1]);
            if (pbig) {
                mm32(Zh, Zl, Yh, Yl, acc, P1r, P1c, lane);
                epi_half(acc[0], Th, Tl, -0.5f, 1.5f, P1r, P1c, lane, P1m);
                epi_half(acc[1], Th, Tl, -0.5f, 1.5f, P1r + 16, P1c, lane, P1m);
            } else if (p1act) {
                mm_half(Zh, Zl, Yh, Yl, acc[0], P1r, P1c, lane);
                epi_half(acc[0], Th, Tl, -0.5f, 1.5f, P1r, P1c, lane, P1m);
            }
        }
        __syncthreads();

        if (it < 4) {
            // P2: 20 m32 tasks (Y@T tiles 0-9, Z@T tiles 0-9)
            float accB[2][4][4];
            zero4(acc[0]); zero4(acc[1]);
            if (z2a) mm32(Zh, Zl, Th, Tl, acc, P2ar, P2ac, lane);
            else     mm32(Yh, Yl, Th, Tl, acc, P2ar, P2ac, lane);
            if (has2b) {
                zero4(accB[0]); zero4(accB[1]);
                mm32(Zh, Zl, Th, Tl, accB, P2br, P2bc, lane);
            }
            __syncthreads();
            if (z2a) {
                epi_half(acc[0], Zh, Zl, 1.f, 0.f, P2ar, P2ac, lane, P2am);
                epi_half(acc[1], Zh, Zl, 1.f, 0.f, P2ar + 16, P2ac, lane, P2am);
            } else {
                epi_half(acc[0], Yh, Yl, 1.f, 0.f, P2ar, P2ac, lane, P2am);
                epi_half(acc[1], Yh, Yl, 1.f, 0.f, P2ar + 16, P2ac, lane, P2am);
            }
            if (has2b) {
                epi_half(accB[0], Zh, Zl, 1.f, 0.f, P2br, P2bc, lane, P2bm);
                epi_half(accB[1], Zh, Zl, 1.f, 0.f, P2br + 16, P2bc, lane, P2bm);
            }
            __syncthreads();
        } else {
            // Last: Y5 = Y@T full grid (16 m32 tiles), straight to GMEM
            const float s = sqrtf(normA);
            zero4(acc[0]); zero4(acc[1]);
            mm32(Yh, Yl, Th, Tl, acc, Lr, Lc, lane);
            epi_out_half(acc[0], Ob, s, Lr, Lc, lane);
            epi_out_half(acc[1], Ob, s, Lr + 16, Lc, lane);
        }
    }
}

extern "C" void kernel_launch(void* const* d_in, const int* in_sizes, int n_in,
                              void* d_out, int out_size) {
    const float* A = (const float*)d_in[0];
    float* out = (float*)d_out;
    const int nbatch = in_sizes[0] / (NMAT * NMAT);            // 1024
    const size_t smem = 6 * 128 * PITCH32 * sizeof(uint32_t);  // 208896 B
    cudaFuncSetAttribute(ns_m32_kernel,
                         cudaFuncAttributeMaxDynamicSharedMemorySize, (int)smem);
    ns_m32_kernel<<<nbatch, NT, smem>>>(A, out);
}